// round 16
// baseline (speedup 1.0000x reference)
#include <cuda_runtime.h>

// GlitchSampler: masked scatter of random glitch windows into X, plus y labels.
//
// R16 = R15 (locked best: 8.16-8.19us) + smem realignment of the masked
// unaligned path — the last non-vector global traffic in the kernel:
//   - old: 16 scalar LDG.32 + 16 STG.32 per thread for misaligned windows.
//   - new: round window base down to 16B; block bulk-loads 1025 float4s as
//     fully aligned LDG.128 + L2::256B prefetch (same profile as the fast
//     unmasked path) into smem; __syncthreads; each thread reads its 4
//     floats at the 4B misalignment from smem (LDS, 29cyc, <=4-way conflict)
//     and writes aligned STG.128.
//   All global accesses are now 16B vector ops with 256B prefetch.
//   Bounds: aligned base >= glitch row start (round-down); max read
//   base+4100 floats <= 8703+4100 < 16384 (row length). Smem 16.4KB/block;
//   thread limit (8 blocks/SM) still binding, occupancy unchanged.
//
// Shapes: X [512,2,4096] f32, y [512] f32, glitch_{h,l} [2048,16384] f32,
//         masks/idx/starts [2,512] int32.
// Output: concat(Xo.flatten(), yo.flatten()) = 4,194,304 + 512 f32.

#define Bn 512
#define Cn 2
#define Kn 4096
#define Tn 16384
#define MIN_START 3584
#define TPB 256

__device__ __forceinline__ float4 ldg_pf4(const float4* p)
{
    float4 v;
    asm volatile("ld.global.nc.L2::256B.v4.f32 {%0,%1,%2,%3}, [%4];"
                 : "=f"(v.x), "=f"(v.y), "=f"(v.z), "=f"(v.w)
                 : "l"(p));
    return v;
}

__global__ void __launch_bounds__(TPB)
glitch_sampler_kernel(const float* __restrict__ X,
                      const float* __restrict__ y,
                      const float* __restrict__ gh,
                      const float* __restrict__ gl,
                      const int*   __restrict__ masks,
                      const int*   __restrict__ idx,
                      const int*   __restrict__ starts,
                      float* __restrict__ out)
{
    __shared__ float4 sm[Kn / 4 + 1];           // 1025 float4 = 16,400 B

    const int row = blockIdx.x;                 // 0..1023 rows; block 1024 = y tail
    const int tid = threadIdx.x;

    if (row < Bn * Cn) {
        const int b  = row >> 1;                // X layout [B,C,K]: row = b*2 + c
        const int c  = row & 1;
        const int cb = c * Bn + b;              // metadata layout [C,B]

        // front-load ALL metadata (no branch-dependent loads)
        const int m  = masks[cb];
        const int gi = idx[cb];
        const int gs = starts[cb];

        // both candidate sources computed before the branch
        const float* __restrict__ g   = (c == 0) ? gh : gl;
        const float* __restrict__ gsv = g + (long)gi * Tn + (gs + MIN_START);
        const float* __restrict__ xs  = X + (long)row * Kn;

        float* __restrict__ dstf = out + (long)row * Kn;
        float4* __restrict__ d4  = (float4*)dstf + tid;

        const float* srcf = m ? gsv : xs;
        const unsigned misalign = (unsigned)((size_t)srcf & 15u) >> 2;  // 0..3 floats

        if (misalign == 0) {
            // aligned float4 copy: 4 front-batched prefetching loads, 4 stores
            const float4* __restrict__ s4 = (const float4*)srcf + tid;
            float4 v0 = ldg_pf4(s4 +   0);
            float4 v1 = ldg_pf4(s4 + 256);
            float4 v2 = ldg_pf4(s4 + 512);
            float4 v3 = ldg_pf4(s4 + 768);
            d4[0]   = v0;
            d4[256] = v1;
            d4[512] = v2;
            d4[768] = v3;
        } else {
            // realign via smem: bulk aligned vector load of 1025 float4s
            // covering [base, base + 4100 floats), then shifted smem read.
            const float4* __restrict__ ab =
                (const float4*)((size_t)srcf & ~(size_t)15);
            #pragma unroll
            for (int j = 0; j < 4; ++j)
                sm[tid + 256 * j] = ldg_pf4(ab + tid + 256 * j);
            if (tid == 0)
                sm[1024] = ldg_pf4(ab + 1024);
            __syncthreads();

            const float* __restrict__ smf = (const float*)sm + misalign;
            #pragma unroll
            for (int j = 0; j < 4; ++j) {
                const int f0 = (tid + 256 * j) * 4;
                d4[256 * j] = make_float4(smf[f0], smf[f0 + 1],
                                          smf[f0 + 2], smf[f0 + 3]);
            }
        }
    } else {
        // tail block: y output (512 elements, 256 threads x 2)
        #pragma unroll
        for (int i = 0; i < Bn / TPB; ++i) {
            const int b = i * TPB + tid;
            float v = y[b];
            if (masks[0 * Bn + b] != 0) v -= 2.0f;
            if (masks[1 * Bn + b] != 0) v -= 4.0f;
            out[(long)Bn * Cn * Kn + b] = v;
        }
    }
}

extern "C" void kernel_launch(void* const* d_in, const int* in_sizes, int n_in,
                              void* d_out, int out_size)
{
    const float* X      = (const float*)d_in[0];
    const float* y      = (const float*)d_in[1];
    const float* gh     = (const float*)d_in[2];
    const float* gl     = (const float*)d_in[3];
    const int*   masks  = (const int*)  d_in[4];
    const int*   idx    = (const int*)  d_in[5];
    const int*   starts = (const int*)  d_in[6];
    float* out = (float*)d_out;

    glitch_sampler_kernel<<<Bn * Cn + 1, TPB>>>(X, y, gh, gl, masks, idx, starts, out);
}